// round 1
// baseline (speedup 1.0000x reference)
#include <cuda_runtime.h>
#include <cstdint>

#define NN   50000
#define EE   800000
#define FIN  128
#define DD   256
#define LL   3
#define GG   512
#define BN_EPS 1e-5f

// ---------------- scratch (device globals; no runtime allocation) ----------
__device__ __align__(256) float g_h[(size_t)NN * DD];   // current node features
__device__ __align__(256) float g_z[(size_t)NN * DD];   // z buffer (h+agg, then z2, then relu(bn))
__device__ __align__(256) float g_t[(size_t)NN * DD];   // relu(z@W1+b1)
__device__ __align__(256) float g_colsum[DD];
__device__ __align__(256) float g_colsq[DD];
__device__ __align__(256) float g_scale[DD];
__device__ __align__(256) float g_shift[DD];
__device__ __align__(256) float g_pooled[(size_t)GG * DD * LL];
__device__ __align__(256) float g_cnt[GG];
__device__ __align__(256) float g_hid[(size_t)GG * (DD / 2)];

// vectorized fire-and-forget global atomic add (sm_90+)
__device__ __forceinline__ void red_add_v4(float* p, float4 v) {
    asm volatile("red.global.add.v4.f32 [%0], {%1,%2,%3,%4};"
                 :: "l"(p), "f"(v.x), "f"(v.y), "f"(v.z), "f"(v.w)
                 : "memory");
}

// ---------------- small setup kernels --------------------------------------
__global__ void zero_small_kernel() {
    int i = blockIdx.x * blockDim.x + threadIdx.x;
    if (i < GG * DD * LL) g_pooled[i] = 0.f;
    if (i < GG)           g_cnt[i]    = 0.f;
}

__global__ void count_nodes_kernel(const int* __restrict__ batch) {
    int i = blockIdx.x * blockDim.x + threadIdx.x;
    if (i < NN) atomicAdd(&g_cnt[batch[i]], 1.0f);
}

// ---------------- SGEMM: C = [relu](A @ W + bias), optional dual write -----
// BM=BN=128, BK=8, 256 threads, 8x8 micro-tile per thread.
template <int RELU, int DUAL>
__global__ __launch_bounds__(256)
void sgemm_kernel(const float* __restrict__ A, const float* __restrict__ W,
                  const float* __restrict__ bias,
                  float* __restrict__ C, float* __restrict__ C2,
                  int M, int K, int Nc) {
    __shared__ float As[8][128];
    __shared__ float Bs[8][128];

    const int tid  = threadIdx.x;
    const int bm   = blockIdx.y * 128;
    const int bn   = blockIdx.x * 128;
    const int arow = tid >> 1;            // 0..127
    const int acol = (tid & 1) * 4;       // 0 or 4
    const int brow = tid >> 5;            // 0..7
    const int bcol = (tid & 31) * 4;      // 0..124
    const int tr   = (tid >> 4) * 8;      // 0..120
    const int tc   = (tid & 15) * 8;      // 0..120

    float acc[8][8];
#pragma unroll
    for (int i = 0; i < 8; i++)
#pragma unroll
        for (int j = 0; j < 8; j++) acc[i][j] = 0.f;

    const int gr = bm + arow;
    const bool arow_ok = (gr < M);
    const float* Ap = A + (size_t)gr * K + acol;

    for (int k0 = 0; k0 < K; k0 += 8) {
        float4 av = arow_ok ? *(const float4*)(Ap + k0) : make_float4(0.f, 0.f, 0.f, 0.f);
        As[acol + 0][arow] = av.x;
        As[acol + 1][arow] = av.y;
        As[acol + 2][arow] = av.z;
        As[acol + 3][arow] = av.w;
        *(float4*)&Bs[brow][bcol] = *(const float4*)&W[(size_t)(k0 + brow) * Nc + bn + bcol];
        __syncthreads();

#pragma unroll
        for (int kk = 0; kk < 8; kk++) {
            float4 a0 = *(const float4*)&As[kk][tr];
            float4 a1 = *(const float4*)&As[kk][tr + 4];
            float4 b0 = *(const float4*)&Bs[kk][tc];
            float4 b1 = *(const float4*)&Bs[kk][tc + 4];
            float ar[8] = {a0.x, a0.y, a0.z, a0.w, a1.x, a1.y, a1.z, a1.w};
            float br[8] = {b0.x, b0.y, b0.z, b0.w, b1.x, b1.y, b1.z, b1.w};
#pragma unroll
            for (int i = 0; i < 8; i++)
#pragma unroll
                for (int j = 0; j < 8; j++)
                    acc[i][j] = fmaf(ar[i], br[j], acc[i][j]);
        }
        __syncthreads();
    }

    float bv[8];
#pragma unroll
    for (int j = 0; j < 8; j++) bv[j] = bias[bn + tc + j];

#pragma unroll
    for (int i = 0; i < 8; i++) {
        int r = bm + tr + i;
        if (r < M) {
            float4 v0, v1;
            v0.x = acc[i][0] + bv[0]; v0.y = acc[i][1] + bv[1];
            v0.z = acc[i][2] + bv[2]; v0.w = acc[i][3] + bv[3];
            v1.x = acc[i][4] + bv[4]; v1.y = acc[i][5] + bv[5];
            v1.z = acc[i][6] + bv[6]; v1.w = acc[i][7] + bv[7];
            if (RELU) {
                v0.x = fmaxf(v0.x, 0.f); v0.y = fmaxf(v0.y, 0.f);
                v0.z = fmaxf(v0.z, 0.f); v0.w = fmaxf(v0.w, 0.f);
                v1.x = fmaxf(v1.x, 0.f); v1.y = fmaxf(v1.y, 0.f);
                v1.z = fmaxf(v1.z, 0.f); v1.w = fmaxf(v1.w, 0.f);
            }
            size_t off = (size_t)r * Nc + bn + tc;
            *(float4*)&C[off]     = v0;
            *(float4*)&C[off + 4] = v1;
            if (DUAL) {
                *(float4*)&C2[off]     = v0;
                *(float4*)&C2[off + 4] = v1;
            }
        }
    }
}

// ---------------- edge scatter: g_z[dst] += g_h[src] ------------------------
__global__ __launch_bounds__(256)
void scatter_kernel(const int* __restrict__ ei) {
    const int* __restrict__ src = ei;
    const int* __restrict__ dst = ei + EE;
    int w    = (blockIdx.x * blockDim.x + threadIdx.x) >> 5;
    int lane = threadIdx.x & 31;
    int nw   = (gridDim.x * blockDim.x) >> 5;
    for (int e = w; e < EE; e += nw) {
        int s = src[e];
        int d = dst[e];
        const float4* hp = (const float4*)(g_h + (size_t)s * DD);
        float* zp = g_z + (size_t)d * DD;
        float4 v0 = hp[lane];
        float4 v1 = hp[lane + 32];
        red_add_v4(zp + lane * 4, v0);
        red_add_v4(zp + 128 + lane * 4, v1);
    }
}

// ---------------- BatchNorm statistics --------------------------------------
__global__ void zero_stats_kernel() {
    int i = threadIdx.x;
    if (i < DD) { g_colsum[i] = 0.f; g_colsq[i] = 0.f; }
}

__global__ __launch_bounds__(DD)
void col_stats_kernel(const float* __restrict__ Z) {
    int c   = threadIdx.x;
    int per = (NN + gridDim.x - 1) / gridDim.x;
    int r0  = blockIdx.x * per;
    int r1  = r0 + per; if (r1 > NN) r1 = NN;
    float s = 0.f, q = 0.f;
    for (int r = r0; r < r1; r++) {
        float v = Z[(size_t)r * DD + c];
        s += v;
        q = fmaf(v, v, q);
    }
    atomicAdd(&g_colsum[c], s);
    atomicAdd(&g_colsq[c],  q);
}

__global__ void finalize_stats_kernel(const float* __restrict__ gamma,
                                      const float* __restrict__ beta) {
    int c = threadIdx.x;
    float mean = g_colsum[c] * (1.0f / NN);
    float var  = g_colsq[c] * (1.0f / NN) - mean * mean;
    float sc   = gamma[c] * rsqrtf(var + BN_EPS);
    g_scale[c] = sc;
    g_shift[c] = beta[c] - mean * sc;
}

// ---------------- BN apply + ReLU + dual-write + pooled sum -----------------
__global__ __launch_bounds__(256)
void bn_apply_kernel(const int* __restrict__ batch, int layer) {
    int row = blockIdx.x * 4 + (threadIdx.x >> 6);
    if (row >= NN) return;
    int c4 = (threadIdx.x & 63) * 4;
    float4 v  = *(const float4*)&g_z[(size_t)row * DD + c4];
    float4 sc = *(const float4*)&g_scale[c4];
    float4 sh = *(const float4*)&g_shift[c4];
    float4 o;
    o.x = fmaxf(fmaf(v.x, sc.x, sh.x), 0.f);
    o.y = fmaxf(fmaf(v.y, sc.y, sh.y), 0.f);
    o.z = fmaxf(fmaf(v.z, sc.z, sh.z), 0.f);
    o.w = fmaxf(fmaf(v.w, sc.w, sh.w), 0.f);
    *(float4*)&g_h[(size_t)row * DD + c4] = o;
    *(float4*)&g_z[(size_t)row * DD + c4] = o;   // ready for next layer's scatter
    int gidx = batch[row];
    red_add_v4(&g_pooled[(size_t)gidx * (DD * LL) + layer * DD + c4], o);
}

// ---------------- MLP head --------------------------------------------------
__global__ __launch_bounds__(128)
void fc1_kernel(const float* __restrict__ W, const float* __restrict__ b) {
    int row = blockIdx.x;
    int j   = threadIdx.x;   // 0..127
    __shared__ float sp[DD * LL];
    for (int k = j; k < DD * LL; k += 128)
        sp[k] = g_pooled[(size_t)row * (DD * LL) + k];
    __syncthreads();
    float inv = 1.0f / fmaxf(g_cnt[row], 1.0f);
    float s = 0.f;
#pragma unroll 8
    for (int k = 0; k < DD * LL; k++)
        s = fmaf(sp[k], W[(size_t)k * 128 + j], s);
    g_hid[(size_t)row * 128 + j] = fmaxf(fmaf(s, inv, b[j]), 0.f);
}

__global__ __launch_bounds__(128)
void fc2_kernel(const float* __restrict__ W, const float* __restrict__ b,
                float* __restrict__ out) {
    int row = blockIdx.x;
    int t   = threadIdx.x;  // 0..127
    float v = g_hid[(size_t)row * 128 + t] * W[t];
#pragma unroll
    for (int off = 16; off; off >>= 1)
        v += __shfl_down_sync(0xFFFFFFFFu, v, off);
    __shared__ float ws[4];
    if ((t & 31) == 0) ws[t >> 5] = v;
    __syncthreads();
    if (t == 0) out[row] = ws[0] + ws[1] + ws[2] + ws[3] + b[0];
}

// ---------------- launch ----------------------------------------------------
extern "C" void kernel_launch(void* const* d_in, const int* in_sizes, int n_in,
                              void* d_out, int out_size) {
    const float* x     = (const float*)d_in[0];
    const int*   ei    = (const int*)d_in[1];
    const int*   batch = (const int*)d_in[2];
    // num_graphs may or may not be materialized as an input tensor.
    int base = n_in - 12;
    const float* W_enc = (const float*)d_in[base + 0];
    const float* b_enc = (const float*)d_in[base + 1];
    const float* W1    = (const float*)d_in[base + 2];
    const float* b1    = (const float*)d_in[base + 3];
    const float* W2    = (const float*)d_in[base + 4];
    const float* b2    = (const float*)d_in[base + 5];
    const float* gamma = (const float*)d_in[base + 6];
    const float* beta  = (const float*)d_in[base + 7];
    const float* Wf1   = (const float*)d_in[base + 8];
    const float* bf1   = (const float*)d_in[base + 9];
    const float* Wf2   = (const float*)d_in[base + 10];
    const float* bf2   = (const float*)d_in[base + 11];
    float* out = (float*)d_out;

    float *ph = nullptr, *pz = nullptr, *pt = nullptr;
    cudaGetSymbolAddress((void**)&ph, g_h);
    cudaGetSymbolAddress((void**)&pz, g_z);
    cudaGetSymbolAddress((void**)&pt, g_t);

    zero_small_kernel<<<(GG * DD * LL + 255) / 256, 256>>>();
    count_nodes_kernel<<<(NN + 255) / 256, 256>>>(batch);

    dim3 ge(DD / 128, (NN + 127) / 128);   // (2, 391)

    // encoder: h = x @ W_enc + b_enc ; dual-write into z for first scatter
    sgemm_kernel<0, 1><<<ge, 256>>>(x, W_enc, b_enc, ph, pz, NN, FIN, DD);

    for (int l = 0; l < LL; l++) {
        scatter_kernel<<<2048, 256>>>(ei);                                   // z += h[src]
        sgemm_kernel<1, 0><<<ge, 256>>>(pz, W1 + (size_t)l * DD * DD, b1 + l * DD,
                                        pt, nullptr, NN, DD, DD);            // t = relu(z@W1+b1)
        sgemm_kernel<0, 0><<<ge, 256>>>(pt, W2 + (size_t)l * DD * DD, b2 + l * DD,
                                        pz, nullptr, NN, DD, DD);            // z = t@W2+b2
        zero_stats_kernel<<<1, 512>>>();
        col_stats_kernel<<<512, DD>>>(pz);
        finalize_stats_kernel<<<1, DD>>>(gamma + l * DD, beta + l * DD);
        bn_apply_kernel<<<NN / 4, 256>>>(batch, l);                          // h=z=relu(bn), pool
    }

    fc1_kernel<<<GG, 128>>>(Wf1, bf1);
    fc2_kernel<<<GG, 128>>>(Wf2, bf2, out);
    (void)in_sizes; (void)out_size;
}

// round 3
// speedup vs baseline: 1.3421x; 1.3421x over previous
#include <cuda_runtime.h>
#include <cuda_bf16.h>
#include <cstdint>

#define NN   50000
#define EE   800000
#define FIN  128
#define DD   256
#define LL   3
#define GG   512
#define BN_EPS 1e-5f

// ======================= helpers ===========================================
__device__ __forceinline__ uint32_t smem_to_u32(const void* smem_ptr) {
    uint32_t addr;
    asm("{ .reg .u64 tmp; cvta.to.shared.u64 tmp, %1; cvt.u32.u64 %0, tmp; }"
        : "=r"(addr) : "l"(smem_ptr));
    return addr;
}
__device__ __forceinline__ void ldsm_x4(uint32_t* r, uint32_t addr) {
    asm volatile("ldmatrix.sync.aligned.m8n8.x4.shared.b16 {%0,%1,%2,%3}, [%4];"
        : "=r"(r[0]), "=r"(r[1]), "=r"(r[2]), "=r"(r[3]) : "r"(addr));
}
__device__ __forceinline__ void mma16816(float* d, const uint32_t* a,
                                         const uint32_t* b) {
    asm volatile(
        "mma.sync.aligned.m16n8k16.row.col.f32.bf16.bf16.f32 "
        "{%0,%1,%2,%3}, {%4,%5,%6,%7}, {%8,%9}, {%0,%1,%2,%3};"
        : "+f"(d[0]), "+f"(d[1]), "+f"(d[2]), "+f"(d[3])
        : "r"(a[0]), "r"(a[1]), "r"(a[2]), "r"(a[3]), "r"(b[0]), "r"(b[1]));
}
__device__ __forceinline__ void split2(float x, float y, uint32_t& h, uint32_t& l) {
    __nv_bfloat16 hx = __float2bfloat16(x), hy = __float2bfloat16(y);
    __nv_bfloat16 lx = __float2bfloat16(x - __bfloat162float(hx));
    __nv_bfloat16 ly = __float2bfloat16(y - __bfloat162float(hy));
    __nv_bfloat162 hh = __halves2bfloat162(hx, hy);
    __nv_bfloat162 ll = __halves2bfloat162(lx, ly);
    h = *reinterpret_cast<uint32_t*>(&hh);
    l = *reinterpret_cast<uint32_t*>(&ll);
}
__device__ __forceinline__ void red_add_v4(float* p, float4 v) {
    asm volatile("red.global.add.v4.f32 [%0], {%1,%2,%3,%4};"
                 :: "l"(p), "f"(v.x), "f"(v.y), "f"(v.z), "f"(v.w)
                 : "memory");
}
// ldmatrix-friendly chunk swizzle: 16B-chunk index within a 128x32 bf16 tile
#define CIDX(row, c8) ((row) * 4 + ((c8) ^ ((row) & 3)))

// ======================= scratch (device globals) ===========================
__device__ __align__(256) float g_h[(size_t)NN * DD];
__device__ __align__(256) float g_z[(size_t)NN * DD];
__device__ __align__(256) float g_t[(size_t)NN * DD];
__device__ __align__(256) float g_colsum[DD];
__device__ __align__(256) float g_colsq[DD];
__device__ __align__(256) float g_scale[DD];
__device__ __align__(256) float g_shift[DD];
__device__ __align__(256) float g_pooled[(size_t)GG * DD * LL];
__device__ __align__(256) float g_cnt[GG];
__device__ __align__(256) float g_hid[(size_t)GG * (DD / 2)];
// pre-split, pre-swizzled weights, n-major tiles:
// layout: slot(7) x nblk(2) x kchunk(8) x [128 rows x 4 chunks x 16B] (8KB tile)
__device__ __align__(256) __nv_bfloat16 g_Bhi[7 * 65536];
__device__ __align__(256) __nv_bfloat16 g_Blo[7 * 65536];

// ======================= weight prep ========================================
// W[K,256] row-major -> n-major swizzled bf16 hi/lo tiles
__global__ void prep_weight_kernel(const float* __restrict__ W, int slot, int K) {
    int idx = blockIdx.x * blockDim.x + threadIdx.x;   // idx = kk*256 + n
    if (idx >= K * 256) return;
    int kk = idx >> 8;
    int n  = idx & 255;
    float w = W[idx];
    __nv_bfloat16 hi = __float2bfloat16(w);
    __nv_bfloat16 lo = __float2bfloat16(w - __bfloat162float(hi));
    int nblk = n >> 7, nr = n & 127;
    int kchunk = kk >> 5, kc = kk & 31;
    int c8 = kc >> 3, w8 = kc & 7;
    size_t off = (size_t)slot * 65536 + ((size_t)nblk * 8 + kchunk) * 4096
               + (size_t)CIDX(nr, c8) * 8 + w8;        // in bf16 elements
    g_Bhi[off] = hi;
    g_Blo[off] = lo;
}

// ======================= split-bf16 mma.sync GEMM ===========================
// C[M,256] = A[M,K] @ W_slot[K,256] + bias, optional relu / dual write
template <int RELU, int DUAL>
__global__ __launch_bounds__(256, 1)
void mma_gemm_kernel(const float* __restrict__ A, int K, int slot,
                     const float* __restrict__ bias,
                     float* __restrict__ C, float* __restrict__ C2, int M) {
    __shared__ uint4 sAhi[512], sAlo[512], sBhi[512], sBlo[512];

    const int tid  = threadIdx.x;
    const int wid  = tid >> 5, lane = tid & 31;
    const int bm   = blockIdx.y * 128;
    const int bn   = blockIdx.x * 128;
    const int wm   = (wid & 3) * 32;
    const int wn   = (wid >> 2) * 64;
    const int nChunks = K >> 5;

    const uint32_t aHi = smem_to_u32(sAhi);
    const uint32_t aLo = smem_to_u32(sAlo);
    const uint32_t bHi = smem_to_u32(sBhi);
    const uint32_t bLo = smem_to_u32(sBlo);

    // ldmatrix lane geometry
    int arow[2];
    arow[0] = wm + (lane & 15);
    arow[1] = wm + 16 + (lane & 15);
    const int ac8 = lane >> 4;                 // 0/1 (k half)
    int brow[4];
#pragma unroll
    for (int nt2 = 0; nt2 < 4; nt2++)
        brow[nt2] = wn + nt2 * 16 + (lane >> 4) * 8 + (lane & 7);
    const int bc8 = (lane >> 3) & 1;

    // A loading geometry: thread handles row tid>>1, 16 cols at (tid&1)*16
    const int lrow = tid >> 1;
    const int lcsel = tid & 1;
    const bool lok = (bm + lrow) < M;
    const float* ap = A + (size_t)(bm + lrow) * K + lcsel * 16;

    float acc[2][8][4];
#pragma unroll
    for (int mt = 0; mt < 2; mt++)
#pragma unroll
        for (int nt = 0; nt < 8; nt++)
#pragma unroll
            for (int i = 0; i < 4; i++) acc[mt][nt][i] = 0.f;

    const uint4* bsrc_hi = (const uint4*)(g_Bhi + (size_t)slot * 65536
                                          + (size_t)blockIdx.x * 8 * 4096);
    const uint4* bsrc_lo = (const uint4*)(g_Blo + (size_t)slot * 65536
                                          + (size_t)blockIdx.x * 8 * 4096);

    for (int c = 0; c < nChunks; c++) {
        // ---- A chunk: fp32 -> bf16 hi/lo split, swizzled store ----
#pragma unroll
        for (int s = 0; s < 2; s++) {
            float4 va = lok ? *(const float4*)(ap + c * 32 + s * 8)
                            : make_float4(0.f, 0.f, 0.f, 0.f);
            float4 vb = lok ? *(const float4*)(ap + c * 32 + s * 8 + 4)
                            : make_float4(0.f, 0.f, 0.f, 0.f);
            uint4 h, l;
            split2(va.x, va.y, h.x, l.x);
            split2(va.z, va.w, h.y, l.y);
            split2(vb.x, vb.y, h.z, l.z);
            split2(vb.z, vb.w, h.w, l.w);
            int ci = CIDX(lrow, lcsel * 2 + s);
            sAhi[ci] = h;
            sAlo[ci] = l;
        }
        // ---- B chunk: straight copy of pre-swizzled tile (8KB each) ----
        {
            const uint4* sh = bsrc_hi + (size_t)c * 512;
            const uint4* sl = bsrc_lo + (size_t)c * 512;
            sBhi[tid]       = sh[tid];
            sBhi[tid + 256] = sh[tid + 256];
            sBlo[tid]       = sl[tid];
            sBlo[tid + 256] = sl[tid + 256];
        }
        __syncthreads();

#pragma unroll
        for (int kk2 = 0; kk2 < 2; kk2++) {
            uint32_t Ah[2][4], Al[2][4], Bh[4][4], Bl[4][4];
#pragma unroll
            for (int mt = 0; mt < 2; mt++) {
                int ci = CIDX(arow[mt], kk2 * 2 + ac8);
                ldsm_x4(Ah[mt], aHi + ci * 16);
                ldsm_x4(Al[mt], aLo + ci * 16);
            }
#pragma unroll
            for (int nt2 = 0; nt2 < 4; nt2++) {
                int ci = CIDX(brow[nt2], kk2 * 2 + bc8);
                ldsm_x4(Bh[nt2], bHi + ci * 16);
                ldsm_x4(Bl[nt2], bLo + ci * 16);
            }
#pragma unroll
            for (int mt = 0; mt < 2; mt++)
#pragma unroll
                for (int nt = 0; nt < 8; nt++) {
                    const uint32_t* ph = &Bh[nt >> 1][(nt & 1) * 2];
                    const uint32_t* pl = &Bl[nt >> 1][(nt & 1) * 2];
                    mma16816(acc[mt][nt], Ah[mt], ph);   // hi*hi
                    mma16816(acc[mt][nt], Ah[mt], pl);   // hi*lo
                    mma16816(acc[mt][nt], Al[mt], ph);   // lo*hi
                }
        }
        __syncthreads();
    }

    // ---- epilogue ----
    const int col0 = bn + wn + (lane & 3) * 2;
    float2 bv[8];
#pragma unroll
    for (int nt = 0; nt < 8; nt++)
        bv[nt] = *(const float2*)&bias[col0 + nt * 8];

#pragma unroll
    for (int mt = 0; mt < 2; mt++) {
        int ra = bm + wm + mt * 16 + (lane >> 2);
#pragma unroll
        for (int half = 0; half < 2; half++) {
            int r = ra + half * 8;
            if (r < M) {
                size_t rowoff = (size_t)r * 256;
#pragma unroll
                for (int nt = 0; nt < 8; nt++) {
                    float2 o;
                    o.x = acc[mt][nt][half * 2 + 0] + bv[nt].x;
                    o.y = acc[mt][nt][half * 2 + 1] + bv[nt].y;
                    if (RELU) { o.x = fmaxf(o.x, 0.f); o.y = fmaxf(o.y, 0.f); }
                    *(float2*)&C[rowoff + col0 + nt * 8] = o;
                    if (DUAL) *(float2*)&C2[rowoff + col0 + nt * 8] = o;
                }
            }
        }
    }
}

// ======================= small kernels ======================================
__global__ void zero_small_kernel() {
    int i = blockIdx.x * blockDim.x + threadIdx.x;
    if (i < GG * DD * LL) g_pooled[i] = 0.f;
    if (i < GG)           g_cnt[i]    = 0.f;
}

__global__ void count_nodes_kernel(const int* __restrict__ batch) {
    int i = blockIdx.x * blockDim.x + threadIdx.x;
    if (i < NN) atomicAdd(&g_cnt[batch[i]], 1.0f);
}

__global__ __launch_bounds__(256)
void scatter_kernel(const int* __restrict__ ei) {
    const int* __restrict__ src = ei;
    const int* __restrict__ dst = ei + EE;
    int w    = (blockIdx.x * blockDim.x + threadIdx.x) >> 5;
    int lane = threadIdx.x & 31;
    int nw   = (gridDim.x * blockDim.x) >> 5;
    for (int e = w; e < EE; e += nw) {
        int s = src[e];
        int d = dst[e];
        const float4* hp = (const float4*)(g_h + (size_t)s * DD);
        float* zp = g_z + (size_t)d * DD;
        float4 v0 = hp[lane];
        float4 v1 = hp[lane + 32];
        red_add_v4(zp + lane * 4, v0);
        red_add_v4(zp + 128 + lane * 4, v1);
    }
}

__global__ void zero_stats_kernel() {
    int i = threadIdx.x;
    if (i < DD) { g_colsum[i] = 0.f; g_colsq[i] = 0.f; }
}

__global__ __launch_bounds__(DD)
void col_stats_kernel(const float* __restrict__ Z) {
    int c   = threadIdx.x;
    int per = (NN + gridDim.x - 1) / gridDim.x;
    int r0  = blockIdx.x * per;
    int r1  = r0 + per; if (r1 > NN) r1 = NN;
    float s = 0.f, q = 0.f;
    for (int r = r0; r < r1; r++) {
        float v = Z[(size_t)r * DD + c];
        s += v;
        q = fmaf(v, v, q);
    }
    atomicAdd(&g_colsum[c], s);
    atomicAdd(&g_colsq[c],  q);
}

__global__ void finalize_stats_kernel(const float* __restrict__ gamma,
                                      const float* __restrict__ beta) {
    int c = threadIdx.x;
    float mean = g_colsum[c] * (1.0f / NN);
    float var  = g_colsq[c] * (1.0f / NN) - mean * mean;
    float sc   = gamma[c] * rsqrtf(var + BN_EPS);
    g_scale[c] = sc;
    g_shift[c] = beta[c] - mean * sc;
}

__global__ __launch_bounds__(256)
void bn_apply_kernel(const int* __restrict__ batch, int layer) {
    int row = blockIdx.x * 4 + (threadIdx.x >> 6);
    if (row >= NN) return;
    int c4 = (threadIdx.x & 63) * 4;
    float4 v  = *(const float4*)&g_z[(size_t)row * DD + c4];
    float4 sc = *(const float4*)&g_scale[c4];
    float4 sh = *(const float4*)&g_shift[c4];
    float4 o;
    o.x = fmaxf(fmaf(v.x, sc.x, sh.x), 0.f);
    o.y = fmaxf(fmaf(v.y, sc.y, sh.y), 0.f);
    o.z = fmaxf(fmaf(v.z, sc.z, sh.z), 0.f);
    o.w = fmaxf(fmaf(v.w, sc.w, sh.w), 0.f);
    *(float4*)&g_h[(size_t)row * DD + c4] = o;
    *(float4*)&g_z[(size_t)row * DD + c4] = o;
    int gidx = batch[row];
    red_add_v4(&g_pooled[(size_t)gidx * (DD * LL) + layer * DD + c4], o);
}

__global__ __launch_bounds__(128)
void fc1_kernel(const float* __restrict__ W, const float* __restrict__ b) {
    int row = blockIdx.x;
    int j   = threadIdx.x;
    __shared__ float sp[DD * LL];
    for (int k = j; k < DD * LL; k += 128)
        sp[k] = g_pooled[(size_t)row * (DD * LL) + k];
    __syncthreads();
    float inv = 1.0f / fmaxf(g_cnt[row], 1.0f);
    float s = 0.f;
#pragma unroll 8
    for (int k = 0; k < DD * LL; k++)
        s = fmaf(sp[k], W[(size_t)k * 128 + j], s);
    g_hid[(size_t)row * 128 + j] = fmaxf(fmaf(s, inv, b[j]), 0.f);
}

__global__ __launch_bounds__(128)
void fc2_kernel(const float* __restrict__ W, const float* __restrict__ b,
                float* __restrict__ out) {
    int row = blockIdx.x;
    int t   = threadIdx.x;
    float v = g_hid[(size_t)row * 128 + t] * W[t];
#pragma unroll
    for (int off = 16; off; off >>= 1)
        v += __shfl_down_sync(0xFFFFFFFFu, v, off);
    __shared__ float ws[4];
    if ((t & 31) == 0) ws[t >> 5] = v;
    __syncthreads();
    if (t == 0) out[row] = ws[0] + ws[1] + ws[2] + ws[3] + b[0];
}

// ======================= launch ============================================
extern "C" void kernel_launch(void* const* d_in, const int* in_sizes, int n_in,
                              void* d_out, int out_size) {
    const float* x     = (const float*)d_in[0];
    const int*   ei    = (const int*)d_in[1];
    const int*   batch = (const int*)d_in[2];
    int base = n_in - 12;
    const float* W_enc = (const float*)d_in[base + 0];
    const float* b_enc = (const float*)d_in[base + 1];
    const float* W1    = (const float*)d_in[base + 2];
    const float* b1    = (const float*)d_in[base + 3];
    const float* W2    = (const float*)d_in[base + 4];
    const float* b2    = (const float*)d_in[base + 5];
    const float* gamma = (const float*)d_in[base + 6];
    const float* beta  = (const float*)d_in[base + 7];
    const float* Wf1   = (const float*)d_in[base + 8];
    const float* bf1   = (const float*)d_in[base + 9];
    const float* Wf2   = (const float*)d_in[base + 10];
    const float* bf2   = (const float*)d_in[base + 11];
    float* out = (float*)d_out;

    float *ph = nullptr, *pz = nullptr, *pt = nullptr;
    cudaGetSymbolAddress((void**)&ph, g_h);
    cudaGetSymbolAddress((void**)&pz, g_z);
    cudaGetSymbolAddress((void**)&pt, g_t);

    // weight prep (slots: 0=enc, 1..3=W1, 4..6=W2)
    prep_weight_kernel<<<(FIN * 256 + 255) / 256, 256>>>(W_enc, 0, FIN);
    for (int l = 0; l < LL; l++) {
        prep_weight_kernel<<<(DD * 256 + 255) / 256, 256>>>(
            W1 + (size_t)l * DD * DD, 1 + l, DD);
        prep_weight_kernel<<<(DD * 256 + 255) / 256, 256>>>(
            W2 + (size_t)l * DD * DD, 4 + l, DD);
    }

    zero_small_kernel<<<(GG * DD * LL + 255) / 256, 256>>>();
    count_nodes_kernel<<<(NN + 255) / 256, 256>>>(batch);

    dim3 ge(2, (NN + 127) / 128);   // (nblk, 391)

    // encoder: h = x @ W_enc + b_enc (dual-write into z)
    mma_gemm_kernel<0, 1><<<ge, 256>>>(x, FIN, 0, b_enc, ph, pz, NN);

    for (int l = 0; l < LL; l++) {
        scatter_kernel<<<2048, 256>>>(ei);                                  // z += h[src]
        mma_gemm_kernel<1, 0><<<ge, 256>>>(pz, DD, 1 + l, b1 + l * DD,
                                           pt, nullptr, NN);
        mma_gemm_kernel<0, 0><<<ge, 256>>>(pt, DD, 4 + l, b2 + l * DD,
                                           pz, nullptr, NN);
        zero_stats_kernel<<<1, 512>>>();
        col_stats_kernel<<<512, DD>>>(pz);
        finalize_stats_kernel<<<1, DD>>>(gamma + l * DD, beta + l * DD);
        bn_apply_kernel<<<NN / 4, 256>>>(batch, l);
    }

    fc1_kernel<<<GG, 128>>>(Wf1, bf1);
    fc2_kernel<<<GG, 128>>>(Wf2, bf2, out);
    (void)in_sizes; (void)out_size;
}